// round 2
// baseline (speedup 1.0000x reference)
#include <cuda_runtime.h>
#include <math.h>
#include <float.h>

// Problem constants
#define BB   32
#define NNODE 256
#define DD   512
#define HH   8
#define EE   1024
#define EDIM 256
#define GDIM 64
#define HDIM 64
#define BNROWS (BB*NNODE)   // 8192
#define DFF  2048

// ---------------- scratch (device globals; no runtime alloc) ----------------
__device__ float g_xn [BNROWS*DD];
__device__ float g_q  [BNROWS*DD];
__device__ float g_k  [BNROWS*DD];
__device__ float g_v  [BNROWS*DD];
__device__ float g_att[BNROWS*DD];
__device__ float g_x2 [BNROWS*DD];
__device__ float g_ln2[BNROWS*DD];
__device__ float g_h1 [BNROWS*DFF];
__device__ float g_ebias[BB*EE*HH];
__device__ float g_bm[(size_t)BB*HH*NNODE*NNODE];   // fused bias + mask (-FLT_MAX = masked)

// ---------------- LayerNorm: one block per row of 512 ----------------
__global__ void ln_kernel(const float* __restrict__ x, const float* __restrict__ g,
                          const float* __restrict__ b, float* __restrict__ y) {
    int row = blockIdx.x;
    const float* xr = x + (size_t)row * DD;
    float* yr = y + (size_t)row * DD;
    int tid = threadIdx.x; // 128
    float v[4];
    float s = 0.f, s2 = 0.f;
#pragma unroll
    for (int i = 0; i < 4; i++) {
        v[i] = xr[tid + i * 128];
        s += v[i]; s2 += v[i] * v[i];
    }
    __shared__ float rs[4], rs2[4];
    for (int o = 16; o; o >>= 1) {
        s  += __shfl_xor_sync(~0u, s,  o);
        s2 += __shfl_xor_sync(~0u, s2, o);
    }
    int w = tid >> 5;
    if ((tid & 31) == 0) { rs[w] = s; rs2[w] = s2; }
    __syncthreads();
    s  = rs[0] + rs[1] + rs[2] + rs[3];
    s2 = rs2[0] + rs2[1] + rs2[2] + rs2[3];
    float mean = s * (1.f / DD);
    float var  = s2 * (1.f / DD) - mean * mean;
    float r = rsqrtf(var + 1e-5f);
#pragma unroll
    for (int i = 0; i < 4; i++) {
        int c = tid + i * 128;
        yr[c] = (v[i] - mean) * r * g[c] + b[c];
    }
}

// ---------------- Generic tiled fp32 GEMM: C = A(MxK) @ W(NoutxK)^T + bias ----------------
// EPI: 0 = bias only, 1 = +residual, 2 = silu, 3 = +residual then *rowscale
template<int EPI>
__global__ void gemm_kernel(const float* __restrict__ A, const float* __restrict__ W,
                            const float* __restrict__ bias, const float* __restrict__ res,
                            const float* __restrict__ rowscale, float* __restrict__ C,
                            int M, int Nout, int K) {
    __shared__ float As[32][68];
    __shared__ float Bs[32][68];
    int tid = threadIdx.x;            // 256
    int tx = tid & 15, ty = tid >> 4; // 16 x 16 grid of 4x4 microtiles
    int bm0 = blockIdx.y * 64, bn0 = blockIdx.x * 64;
    int arow = tid >> 3;              // 0..31
    int acol = (tid & 7) << 2;        // 0,4,...,28
    float acc[4][4] = {};

    for (int k0 = 0; k0 < K; k0 += 32) {
        float4 a0 = *(const float4*)(A + (size_t)(bm0 + arow)      * K + k0 + acol);
        float4 a1 = *(const float4*)(A + (size_t)(bm0 + arow + 32) * K + k0 + acol);
        float4 b0 = *(const float4*)(W + (size_t)(bn0 + arow)      * K + k0 + acol);
        float4 b1 = *(const float4*)(W + (size_t)(bn0 + arow + 32) * K + k0 + acol);
        float av0[4] = {a0.x, a0.y, a0.z, a0.w};
        float av1[4] = {a1.x, a1.y, a1.z, a1.w};
        float bv0[4] = {b0.x, b0.y, b0.z, b0.w};
        float bv1[4] = {b1.x, b1.y, b1.z, b1.w};
#pragma unroll
        for (int i = 0; i < 4; i++) {
            As[acol + i][arow]      = av0[i];
            As[acol + i][arow + 32] = av1[i];
            Bs[acol + i][arow]      = bv0[i];
            Bs[acol + i][arow + 32] = bv1[i];
        }
        __syncthreads();
#pragma unroll
        for (int kk = 0; kk < 32; kk++) {
            float4 af = *(const float4*)&As[kk][ty << 2];
            float4 bf = *(const float4*)&Bs[kk][tx << 2];
            float a4[4] = {af.x, af.y, af.z, af.w};
            float b4[4] = {bf.x, bf.y, bf.z, bf.w};
#pragma unroll
            for (int i = 0; i < 4; i++)
#pragma unroll
                for (int j = 0; j < 4; j++)
                    acc[i][j] += a4[i] * b4[j];
        }
        __syncthreads();
    }

#pragma unroll
    for (int i = 0; i < 4; i++) {
        int m = bm0 + (ty << 2) + i;
        float rsc = (EPI == 3) ? rowscale[m] : 1.f;
#pragma unroll
        for (int j = 0; j < 4; j++) {
            int n = bn0 + (tx << 2) + j;
            float vv = acc[i][j] + bias[n];
            if (EPI == 1 || EPI == 3) vv += res[(size_t)m * Nout + n];
            if (EPI == 2) vv = vv / (1.f + expf(-vv));
            if (EPI == 3) vv *= rsc;
            C[(size_t)m * Nout + n] = vv;
        }
    }
}

// ---------------- Edge bias: one warp per (b,e) ----------------
__global__ void edge_bias_kernel(const float* __restrict__ rel, const float* __restrict__ geo,
                                 const float* __restrict__ W_eb, const float* __restrict__ b_eb,
                                 const float* __restrict__ geog, const float* __restrict__ geob,
                                 const float* __restrict__ W_geo, const float* __restrict__ b_geo) {
    int warp = (blockIdx.x * blockDim.x + threadIdx.x) >> 5;
    int lane = threadIdx.x & 31;
    if (warp >= BB * EE) return;
    const float* re = rel + (size_t)warp * EDIM;
    const float* ge = geo + (size_t)warp * GDIM;
    float acc[8] = {0, 0, 0, 0, 0, 0, 0, 0};
#pragma unroll
    for (int it = 0; it < 8; it++) {
        int c = (it << 5) + lane;
        float xv = re[c];
#pragma unroll
        for (int h = 0; h < 8; h++) acc[h] += xv * W_eb[h * EDIM + c];
    }
    float g0 = ge[lane], g1 = ge[lane + 32];
    float s = g0 + g1, s2 = g0 * g0 + g1 * g1;
    for (int o = 16; o; o >>= 1) {
        s  += __shfl_xor_sync(~0u, s,  o);
        s2 += __shfl_xor_sync(~0u, s2, o);
    }
    float mean = s * (1.f / 64.f);
    float var  = s2 * (1.f / 64.f) - mean * mean;
    float r = rsqrtf(var + 1e-5f);
    float n0 = (g0 - mean) * r * geog[lane]      + geob[lane];
    float n1 = (g1 - mean) * r * geog[lane + 32] + geob[lane + 32];
#pragma unroll
    for (int h = 0; h < 8; h++)
        acc[h] += n0 * W_geo[h * GDIM + lane] + n1 * W_geo[h * GDIM + lane + 32];
#pragma unroll
    for (int h = 0; h < 8; h++) {
        float v = acc[h];
        for (int o = 16; o; o >>= 1) v += __shfl_xor_sync(~0u, v, o);
        if (lane == h) g_ebias[(size_t)warp * HH + h] = v + b_eb[h] + b_geo[h];
    }
}

// ---------------- init bias/mask tensor: -FLT_MAX everywhere, 0 on diagonal ----------------
__global__ void init_bm_kernel() {
    size_t idx = (size_t)blockIdx.x * blockDim.x + threadIdx.x;
    int j = (int)(idx & 255);
    int i = (int)((idx >> 8) & 255);
    g_bm[idx] = (i == j) ? 0.f : -FLT_MAX;
}

// ---------------- edge scatter (order-preserving: one thread owns one (b,h) plane) ----------------
__global__ void scatter_kernel(const int* __restrict__ edges, const float* __restrict__ emask) {
    int b = blockIdx.x;
    int h = threadIdx.x;
    if (h >= HH) return;
    float* bm = g_bm + ((size_t)b * HH + h) * NNODE * NNODE;
    const float* bias = g_ebias + (size_t)b * EE * HH;
    const int* ed = edges + (size_t)b * EE * 2;
    const float* mk = emask + (size_t)b * EE;
    // pass 1: rb[src,dst] = bias (edge order preserved)
    for (int e = 0; e < EE; e++) {
        if (mk[e] > 0.5f) {
            int s = min(max(ed[2 * e], 0), NNODE - 1);
            int d = min(max(ed[2 * e + 1], 0), NNODE - 1);
            bm[s * NNODE + d] = bias[e * HH + h];
        }
    }
    // pass 2: rb[dst,src] = bias (overwrites pass-1 on collision, matching reference)
    for (int e = 0; e < EE; e++) {
        if (mk[e] > 0.5f) {
            int s = min(max(ed[2 * e], 0), NNODE - 1);
            int d = min(max(ed[2 * e + 1], 0), NNODE - 1);
            bm[d * NNODE + s] = bias[e * HH + h];
        }
    }
}

// ---------------- fused attention: one block per (b,h); K,V resident in smem ----------------
__global__ void attn_kernel(const float* __restrict__ nmask) {
    extern __shared__ float smem[];
    float* ks   = smem;                  // 256*68
    float* vs   = smem + 256 * 68;       // 256*68
    float* qrow = vs + 256 * 68;         // 64
    float* prob = qrow + 64;             // 256
    float* red  = prob + 256;            // 256
    float* scal = red + 256;             // 2

    int bh = blockIdx.x;
    int b = bh >> 3, h = bh & 7;
    int tid = threadIdx.x;               // 256

    for (int idx = tid; idx < 256 * 64; idx += 256) {
        int j = idx >> 6, d = idx & 63;
        size_t off = (size_t)(b * NNODE + j) * DD + h * HDIM + d;
        ks[j * 68 + d] = g_k[off];
        vs[j * 68 + d] = g_v[off];
    }
    float nmJ = nmask[b * NNODE + tid];
    const float* bmBase = g_bm + (size_t)bh * NNODE * NNODE;
    __syncthreads();

    for (int i = 0; i < NNODE; i++) {
        if (tid < 16)
            ((float4*)qrow)[tid] =
                ((const float4*)(g_q + (size_t)(b * NNODE + i) * DD + h * HDIM))[tid];
        __syncthreads();
        float nmI = nmask[b * NNODE + i];
        float bmv = bmBase[(size_t)i * NNODE + tid];
        float sc;
        if (bmv == -FLT_MAX || nmI == 0.f || nmJ == 0.f) {
            sc = -FLT_MAX;
        } else {
            const float4* kr = (const float4*)(ks + tid * 68);
            const float4* qr = (const float4*)qrow;
            float a = 0.f;
#pragma unroll
            for (int t = 0; t < 16; t++) {
                float4 kk = kr[t], qq = qr[t];
                a += kk.x * qq.x + kk.y * qq.y + kk.z * qq.z + kk.w * qq.w;
            }
            sc = a * 0.125f + bmv;
        }
        // row max
        float mx = sc;
        for (int o = 16; o; o >>= 1) mx = fmaxf(mx, __shfl_xor_sync(~0u, mx, o));
        if ((tid & 31) == 0) red[tid >> 5] = mx;
        __syncthreads();
        if (tid < 8) {
            float m2 = red[tid];
            for (int o = 4; o; o >>= 1) m2 = fmaxf(m2, __shfl_xor_sync(0xffu, m2, o));
            if (tid == 0) scal[0] = m2;
        }
        __syncthreads();
        float M = scal[0];
        float p = expf(sc - M);
        prob[tid] = p;
        float ssum = p;
        for (int o = 16; o; o >>= 1) ssum += __shfl_xor_sync(~0u, ssum, o);
        if ((tid & 31) == 0) red[tid >> 5] = ssum;
        __syncthreads();
        if (tid < 8) {
            float s2 = red[tid];
            for (int o = 4; o; o >>= 1) s2 += __shfl_xor_sync(0xffu, s2, o);
            if (tid == 0) scal[1] = s2;
        }
        __syncthreads();
        float inv = 1.f / scal[1];
        // P @ V : thread (qtr, d) accumulates quarter of j-range for one d
        int d = tid & 63, qtr = tid >> 6;
        float a = 0.f;
#pragma unroll 4
        for (int jj = 0; jj < 64; jj++) {
            int j = (qtr << 6) + jj;
            a += prob[j] * vs[j * 68 + d];
        }
        red[tid] = a;
        __syncthreads();
        if (tid < 64) {
            float o = (red[tid] + red[tid + 64] + red[tid + 128] + red[tid + 192]) * inv;
            g_att[(size_t)(b * NNODE + i) * DD + h * HDIM + tid] = o;
        }
        __syncthreads();
    }
}

// ---------------- host launcher ----------------
extern "C" void kernel_launch(void* const* d_in, const int* in_sizes, int n_in,
                              void* d_out, int out_size) {
    const float* x     = (const float*)d_in[0];
    const float* nmask = (const float*)d_in[1];
    const int*   edges = (const int*)  d_in[2];
    const float* emask = (const float*)d_in[3];
    const float* rel   = (const float*)d_in[4];
    const float* geo   = (const float*)d_in[5];
    const float* Wq = (const float*)d_in[6];  const float* bq = (const float*)d_in[7];
    const float* Wk = (const float*)d_in[8];  const float* bk = (const float*)d_in[9];
    const float* Wv = (const float*)d_in[10]; const float* bv = (const float*)d_in[11];
    const float* W_eb = (const float*)d_in[12]; const float* b_eb = (const float*)d_in[13];
    const float* geog = (const float*)d_in[14]; const float* geob = (const float*)d_in[15];
    const float* W_geo = (const float*)d_in[16]; const float* b_geo = (const float*)d_in[17];
    const float* W_out = (const float*)d_in[18]; const float* b_out = (const float*)d_in[19];
    const float* ng = (const float*)d_in[20]; const float* nb = (const float*)d_in[21];
    const float* fg = (const float*)d_in[22]; const float* fb = (const float*)d_in[23];
    const float* W1 = (const float*)d_in[24]; const float* b1 = (const float*)d_in[25];
    const float* W2 = (const float*)d_in[26]; const float* b2 = (const float*)d_in[27];
    float* out = (float*)d_out;

    float *pxn, *pq, *pk, *pv, *patt, *px2, *pln2, *ph1;
    cudaGetSymbolAddress((void**)&pxn,  g_xn);
    cudaGetSymbolAddress((void**)&pq,   g_q);
    cudaGetSymbolAddress((void**)&pk,   g_k);
    cudaGetSymbolAddress((void**)&pv,   g_v);
    cudaGetSymbolAddress((void**)&patt, g_att);
    cudaGetSymbolAddress((void**)&px2,  g_x2);
    cudaGetSymbolAddress((void**)&pln2, g_ln2);
    cudaGetSymbolAddress((void**)&ph1,  g_h1);

    // 1) pre-LN
    ln_kernel<<<BNROWS, 128>>>(x, ng, nb, pxn);
    // 2) Q,K,V projections
    gemm_kernel<0><<<dim3(DD / 64, BNROWS / 64), 256>>>(pxn, Wq, bq, nullptr, nullptr, pq, BNROWS, DD, DD);
    gemm_kernel<0><<<dim3(DD / 64, BNROWS / 64), 256>>>(pxn, Wk, bk, nullptr, nullptr, pk, BNROWS, DD, DD);
    gemm_kernel<0><<<dim3(DD / 64, BNROWS / 64), 256>>>(pxn, Wv, bv, nullptr, nullptr, pv, BNROWS, DD, DD);
    // 3) per-edge bias (eb + geo-LN proj)
    edge_bias_kernel<<<(BB * EE) / 8, 256>>>(rel, geo, W_eb, b_eb, geog, geob, W_geo, b_geo);
    // 4) init fused bias/mask, then ordered scatter
    init_bm_kernel<<<(BB * HH * NNODE * NNODE) / 256, 256>>>();
    scatter_kernel<<<BB, 8>>>(edges, emask);
    // 5) fused attention
    cudaFuncSetAttribute(attn_kernel, cudaFuncAttributeMaxDynamicSharedMemorySize, 141576);
    attn_kernel<<<BB * HH, 256, 141576>>>(nmask);
    // 6) output projection + residual
    gemm_kernel<1><<<dim3(DD / 64, BNROWS / 64), 256>>>(patt, W_out, b_out, x, nullptr, px2, BNROWS, DD, DD);
    // 7) FF block
    ln_kernel<<<BNROWS, 128>>>(px2, fg, fb, pln2);
    gemm_kernel<2><<<dim3(DFF / 64, BNROWS / 64), 256>>>(pln2, W1, b1, nullptr, nullptr, ph1, BNROWS, DFF, DD);
    gemm_kernel<3><<<dim3(DD / 64, BNROWS / 64), 256>>>(ph1, W2, b2, px2, nmask, out, BNROWS, DD, DFF);
}

// round 3
// speedup vs baseline: 1.9969x; 1.9969x over previous
#include <cuda_runtime.h>
#include <math.h>
#include <float.h>

// Problem constants
#define BB    32
#define NNODE 256
#define DD    512
#define HH    8
#define EE    1024
#define EDIM  256
#define GDIM  64
#define HDIM  64
#define BNROWS (BB*NNODE)   // 8192
#define DFF   2048

// ---------------- scratch (device globals; no runtime alloc) ----------------
__device__ float g_xn [BNROWS*DD];
__device__ float g_q  [BNROWS*DD];
__device__ float g_k  [BNROWS*DD];
__device__ float g_v  [BNROWS*DD];
__device__ float g_att[BNROWS*DD];
__device__ float g_x2 [BNROWS*DD];
__device__ float g_ln2[BNROWS*DD];
__device__ float g_h1 [BNROWS*DFF];
__device__ float g_ebias[BB*EE*HH];
__device__ int   g_wmap[BB*NNODE*NNODE];            // winner edge position per (b,i,j)
__device__ float g_bm[(size_t)BB*HH*NNODE*NNODE];   // fused bias + mask (-FLT_MAX = masked)

// ---------------- LayerNorm: one block per row of 512 ----------------
__global__ void ln_kernel(const float* __restrict__ x, const float* __restrict__ g,
                          const float* __restrict__ b, float* __restrict__ y) {
    int row = blockIdx.x;
    const float* xr = x + (size_t)row * DD;
    float* yr = y + (size_t)row * DD;
    int tid = threadIdx.x; // 128
    float v[4];
    float s = 0.f, s2 = 0.f;
#pragma unroll
    for (int i = 0; i < 4; i++) {
        v[i] = xr[tid + i * 128];
        s += v[i]; s2 += v[i] * v[i];
    }
    __shared__ float rs[4], rs2[4];
    for (int o = 16; o; o >>= 1) {
        s  += __shfl_xor_sync(~0u, s,  o);
        s2 += __shfl_xor_sync(~0u, s2, o);
    }
    int w = tid >> 5;
    if ((tid & 31) == 0) { rs[w] = s; rs2[w] = s2; }
    __syncthreads();
    s  = rs[0] + rs[1] + rs[2] + rs[3];
    s2 = rs2[0] + rs2[1] + rs2[2] + rs2[3];
    float mean = s * (1.f / DD);
    float var  = s2 * (1.f / DD) - mean * mean;
    float r = rsqrtf(var + 1e-5f);
#pragma unroll
    for (int i = 0; i < 4; i++) {
        int c = tid + i * 128;
        yr[c] = (v[i] - mean) * r * g[c] + b[c];
    }
}

// ---------------- 128x128x16 tiled fp32 GEMM: C = A(MxK) @ W(NoutxK)^T + bias ----------------
// EPI: 0 = bias only, 1 = +residual, 2 = silu, 3 = +residual then *rowscale
template<int EPI>
__global__ void __launch_bounds__(256, 2)
gemm128(const float* __restrict__ A, const float* __restrict__ W,
        const float* __restrict__ bias, const float* __restrict__ res,
        const float* __restrict__ rowscale, float* __restrict__ C,
        int M, int Nout, int K) {
    __shared__ float As[16][132];
    __shared__ float Bs[16][132];
    int tid = threadIdx.x;                 // 256
    int bm0 = blockIdx.y * 128, bn0 = blockIdx.x * 128;
    int tx = tid & 15, ty = tid >> 4;      // 16 x 16 thread grid, 8x8 microtile
    int lm = tid >> 2;                     // 0..63
    int lv = (tid & 3) << 2;               // 0,4,8,12
    float acc[8][8] = {};

    const float* Ap0 = A + (size_t)(bm0 + lm)      * K + lv;
    const float* Ap1 = A + (size_t)(bm0 + lm + 64) * K + lv;
    const float* Bp0 = W + (size_t)(bn0 + lm)      * K + lv;
    const float* Bp1 = W + (size_t)(bn0 + lm + 64) * K + lv;

    for (int k0 = 0; k0 < K; k0 += 16) {
        float4 a0 = *(const float4*)(Ap0 + k0);
        float4 a1 = *(const float4*)(Ap1 + k0);
        float4 b0 = *(const float4*)(Bp0 + k0);
        float4 b1 = *(const float4*)(Bp1 + k0);
        __syncthreads();
        As[lv + 0][lm] = a0.x; As[lv + 1][lm] = a0.y; As[lv + 2][lm] = a0.z; As[lv + 3][lm] = a0.w;
        As[lv + 0][lm + 64] = a1.x; As[lv + 1][lm + 64] = a1.y; As[lv + 2][lm + 64] = a1.z; As[lv + 3][lm + 64] = a1.w;
        Bs[lv + 0][lm] = b0.x; Bs[lv + 1][lm] = b0.y; Bs[lv + 2][lm] = b0.z; Bs[lv + 3][lm] = b0.w;
        Bs[lv + 0][lm + 64] = b1.x; Bs[lv + 1][lm + 64] = b1.y; Bs[lv + 2][lm + 64] = b1.z; Bs[lv + 3][lm + 64] = b1.w;
        __syncthreads();
#pragma unroll
        for (int kk = 0; kk < 16; kk++) {
            float4 af0 = *(const float4*)&As[kk][ty << 2];
            float4 af1 = *(const float4*)&As[kk][64 + (ty << 2)];
            float4 bf0 = *(const float4*)&Bs[kk][tx << 2];
            float4 bf1 = *(const float4*)&Bs[kk][64 + (tx << 2)];
            float a8[8] = {af0.x, af0.y, af0.z, af0.w, af1.x, af1.y, af1.z, af1.w};
            float b8[8] = {bf0.x, bf0.y, bf0.z, bf0.w, bf1.x, bf1.y, bf1.z, bf1.w};
#pragma unroll
            for (int i = 0; i < 8; i++)
#pragma unroll
                for (int j = 0; j < 8; j++)
                    acc[i][j] += a8[i] * b8[j];
        }
    }

#pragma unroll
    for (int i = 0; i < 8; i++) {
        int m = bm0 + (i < 4 ? (ty << 2) + i : 64 + (ty << 2) + i - 4);
        float rsc = (EPI == 3) ? rowscale[m] : 1.f;
#pragma unroll
        for (int half = 0; half < 2; half++) {
            int n0 = bn0 + (half ? 64 + (tx << 2) : (tx << 2));
            float4 o;
            float* op = &o.x;
#pragma unroll
            for (int j = 0; j < 4; j++) {
                float vv = acc[i][half * 4 + j] + bias[n0 + j];
                if (EPI == 1 || EPI == 3) vv += res[(size_t)m * Nout + n0 + j];
                if (EPI == 2) vv = vv / (1.f + expf(-vv));
                if (EPI == 3) vv *= rsc;
                op[j] = vv;
            }
            *(float4*)(C + (size_t)m * Nout + n0) = o;
        }
    }
}

// ---------------- Edge bias: one warp per (b,e) ----------------
__global__ void edge_bias_kernel(const float* __restrict__ rel, const float* __restrict__ geo,
                                 const float* __restrict__ W_eb, const float* __restrict__ b_eb,
                                 const float* __restrict__ geog, const float* __restrict__ geob,
                                 const float* __restrict__ W_geo, const float* __restrict__ b_geo) {
    int warp = (blockIdx.x * blockDim.x + threadIdx.x) >> 5;
    int lane = threadIdx.x & 31;
    if (warp >= BB * EE) return;
    const float* re = rel + (size_t)warp * EDIM;
    const float* ge = geo + (size_t)warp * GDIM;
    float acc[8] = {0, 0, 0, 0, 0, 0, 0, 0};
#pragma unroll
    for (int it = 0; it < 8; it++) {
        int c = (it << 5) + lane;
        float xv = re[c];
#pragma unroll
        for (int h = 0; h < 8; h++) acc[h] += xv * W_eb[h * EDIM + c];
    }
    float g0 = ge[lane], g1 = ge[lane + 32];
    float s = g0 + g1, s2 = g0 * g0 + g1 * g1;
    for (int o = 16; o; o >>= 1) {
        s  += __shfl_xor_sync(~0u, s,  o);
        s2 += __shfl_xor_sync(~0u, s2, o);
    }
    float mean = s * (1.f / 64.f);
    float var  = s2 * (1.f / 64.f) - mean * mean;
    float r = rsqrtf(var + 1e-5f);
    float n0 = (g0 - mean) * r * geog[lane]      + geob[lane];
    float n1 = (g1 - mean) * r * geog[lane + 32] + geob[lane + 32];
#pragma unroll
    for (int h = 0; h < 8; h++)
        acc[h] += n0 * W_geo[h * GDIM + lane] + n1 * W_geo[h * GDIM + lane + 32];
#pragma unroll
    for (int h = 0; h < 8; h++) {
        float v = acc[h];
        for (int o = 16; o; o >>= 1) v += __shfl_xor_sync(~0u, v, o);
        if (lane == h) g_ebias[(size_t)warp * HH + h] = v + b_eb[h] + b_geo[h];
    }
}

// ---------------- winner map: init to -1 ----------------
__global__ void wmap_init_kernel() {
    int idx = blockIdx.x * 256 + threadIdx.x;
    g_wmap[idx] = -1;
}

// ---------------- parallel ordered-scatter via atomicMax on sequence position ----------------
// pass1 (src,dst) has position e; pass2 (dst,src) has position E+e. Last writer = max position.
__global__ void wmap_scatter_kernel(const int* __restrict__ edges, const float* __restrict__ emask) {
    int t = blockIdx.x * 256 + threadIdx.x;   // B*E
    if (t >= BB * EE) return;
    int b = t >> 10, e = t & 1023;
    if (emask[t] > 0.5f) {
        int s = min(max(edges[2 * t], 0), NNODE - 1);
        int d = min(max(edges[2 * t + 1], 0), NNODE - 1);
        atomicMax(&g_wmap[b * 65536 + s * 256 + d], e);
        atomicMax(&g_wmap[b * 65536 + d * 256 + s], e + EE);
    }
}

// ---------------- dense fill of fused bias/mask (node mask folded in) ----------------
__global__ void bm_fill_kernel(const float* __restrict__ nmask) {
    int idx = blockIdx.x * 256 + threadIdx.x;   // B*N*N
    int j = idx & 255, i = (idx >> 8) & 255, b = idx >> 16;
    int w = g_wmap[idx];
    bool ok = (nmask[b * 256 + i] != 0.f) && (nmask[b * 256 + j] != 0.f) && (w >= 0 || i == j);
    float* bm = g_bm + (size_t)b * HH * 65536 + i * 256 + j;
    if (!ok) {
#pragma unroll
        for (int h = 0; h < HH; h++) bm[(size_t)h * 65536] = -FLT_MAX;
    } else if (w < 0) {
#pragma unroll
        for (int h = 0; h < HH; h++) bm[(size_t)h * 65536] = 0.f;
    } else {
        int e = (w >= EE) ? w - EE : w;
        const float* eb = g_ebias + ((size_t)b * EE + e) * HH;
#pragma unroll
        for (int h = 0; h < HH; h++) bm[(size_t)h * 65536] = eb[h];
    }
}

// ---------------- fused attention: one block per (b,h); warp per query row ----------------
// smem: kt[64][260] (K transposed), vs[256][64], qs[8][64], ps[8][256]
#define KT_PITCH 260
__global__ void attn_kernel() {
    extern __shared__ float smem[];
    float* kt = smem;                       // 64*260
    float* vs = kt + 64 * KT_PITCH;         // 256*64
    float* qs = vs + 256 * 64;              // 8*64
    float* ps = qs + 8 * 64;                // 8*256

    int bh = blockIdx.x;
    int b = bh >> 3, h = bh & 7;
    int tid = threadIdx.x;                  // 256
    int w = tid >> 5, lane = tid & 31;

    for (int idx = tid; idx < 256 * 64; idx += 256) {
        int j = idx >> 6, d = idx & 63;
        size_t off = (size_t)(b * NNODE + j) * DD + h * HDIM + d;
        kt[d * KT_PITCH + j] = g_k[off];
        vs[j * 64 + d]       = g_v[off];
    }
    __syncthreads();

    const float* bmB = g_bm + (size_t)bh * 65536;
    float* psw = ps + w * 256;
    float* qsw = qs + w * 64;

    for (int i = w * 32; i < w * 32 + 32; i++) {
        // stage q row for broadcast reads
        size_t qoff = (size_t)(b * NNODE + i) * DD + h * HDIM;
        qsw[lane]      = g_q[qoff + lane];
        qsw[lane + 32] = g_q[qoff + lane + 32];
        __syncwarp();

        float4 bm0 = *(const float4*)&bmB[i * 256 + (lane << 2)];
        float4 bm1 = *(const float4*)&bmB[i * 256 + 128 + (lane << 2)];

        float s[8] = {0, 0, 0, 0, 0, 0, 0, 0};
#pragma unroll 8
        for (int d = 0; d < 64; d++) {
            float qd = qsw[d];
            float4 k0 = *(const float4*)&kt[d * KT_PITCH + (lane << 2)];
            float4 k1 = *(const float4*)&kt[d * KT_PITCH + 128 + (lane << 2)];
            s[0] += qd * k0.x; s[1] += qd * k0.y; s[2] += qd * k0.z; s[3] += qd * k0.w;
            s[4] += qd * k1.x; s[5] += qd * k1.y; s[6] += qd * k1.z; s[7] += qd * k1.w;
        }
        float sc[8];
        const float* bmv0 = &bm0.x;
        const float* bmv1 = &bm1.x;
#pragma unroll
        for (int r = 0; r < 4; r++) {
            sc[r]     = (bmv0[r] == -FLT_MAX) ? -FLT_MAX : s[r]     * 0.125f + bmv0[r];
            sc[4 + r] = (bmv1[r] == -FLT_MAX) ? -FLT_MAX : s[4 + r] * 0.125f + bmv1[r];
        }
        float mx = sc[0];
#pragma unroll
        for (int r = 1; r < 8; r++) mx = fmaxf(mx, sc[r]);
        for (int o = 16; o; o >>= 1) mx = fmaxf(mx, __shfl_xor_sync(~0u, mx, o));
        float p[8], sum = 0.f;
#pragma unroll
        for (int r = 0; r < 8; r++) { p[r] = expf(sc[r] - mx); sum += p[r]; }
        for (int o = 16; o; o >>= 1) sum += __shfl_xor_sync(~0u, sum, o);
        float inv = 1.f / sum;

        *(float4*)&psw[lane << 2]         = make_float4(p[0], p[1], p[2], p[3]);
        *(float4*)&psw[128 + (lane << 2)] = make_float4(p[4], p[5], p[6], p[7]);
        __syncwarp();

        int d0 = lane << 1;
        float o0 = 0.f, o1 = 0.f;
#pragma unroll 4
        for (int j0 = 0; j0 < 256; j0 += 4) {
            float4 p4 = *(const float4*)&psw[j0];
            float2 v0 = *(const float2*)&vs[(j0 + 0) * 64 + d0];
            float2 v1 = *(const float2*)&vs[(j0 + 1) * 64 + d0];
            float2 v2 = *(const float2*)&vs[(j0 + 2) * 64 + d0];
            float2 v3 = *(const float2*)&vs[(j0 + 3) * 64 + d0];
            o0 += p4.x * v0.x + p4.y * v1.x + p4.z * v2.x + p4.w * v3.x;
            o1 += p4.x * v0.y + p4.y * v1.y + p4.z * v2.y + p4.w * v3.y;
        }
        *(float2*)&g_att[qoff + d0] = make_float2(o0 * inv, o1 * inv);
        __syncwarp();
    }
}

// ---------------- host launcher ----------------
extern "C" void kernel_launch(void* const* d_in, const int* in_sizes, int n_in,
                              void* d_out, int out_size) {
    const float* x     = (const float*)d_in[0];
    const float* nmask = (const float*)d_in[1];
    const int*   edges = (const int*)  d_in[2];
    const float* emask = (const float*)d_in[3];
    const float* rel   = (const float*)d_in[4];
    const float* geo   = (const float*)d_in[5];
    const float* Wq = (const float*)d_in[6];  const float* bq = (const float*)d_in[7];
    const float* Wk = (const float*)d_in[8];  const float* bk = (const float*)d_in[9];
    const float* Wv = (const float*)d_in[10]; const float* bv = (const float*)d_in[11];
    const float* W_eb = (const float*)d_in[12]; const float* b_eb = (const float*)d_in[13];
    const float* geog = (const float*)d_in[14]; const float* geob = (const float*)d_in[15];
    const float* W_geo = (const float*)d_in[16]; const float* b_geo = (const float*)d_in[17];
    const float* W_out = (const float*)d_in[18]; const float* b_out = (const float*)d_in[19];
    const float* ng = (const float*)d_in[20]; const float* nb = (const float*)d_in[21];
    const float* fg = (const float*)d_in[22]; const float* fb = (const float*)d_in[23];
    const float* W1 = (const float*)d_in[24]; const float* b1 = (const float*)d_in[25];
    const float* W2 = (const float*)d_in[26]; const float* b2 = (const float*)d_in[27];
    float* out = (float*)d_out;

    float *pxn, *pq, *pk, *pv, *patt, *px2, *pln2, *ph1;
    cudaGetSymbolAddress((void**)&pxn,  g_xn);
    cudaGetSymbolAddress((void**)&pq,   g_q);
    cudaGetSymbolAddress((void**)&pk,   g_k);
    cudaGetSymbolAddress((void**)&pv,   g_v);
    cudaGetSymbolAddress((void**)&patt, g_att);
    cudaGetSymbolAddress((void**)&px2,  g_x2);
    cudaGetSymbolAddress((void**)&pln2, g_ln2);
    cudaGetSymbolAddress((void**)&ph1,  g_h1);

    // 1) pre-LN
    ln_kernel<<<BNROWS, 128>>>(x, ng, nb, pxn);
    // 2) Q,K,V projections (128x128 tiles)
    gemm128<0><<<dim3(DD / 128, BNROWS / 128), 256>>>(pxn, Wq, bq, nullptr, nullptr, pq, BNROWS, DD, DD);
    gemm128<0><<<dim3(DD / 128, BNROWS / 128), 256>>>(pxn, Wk, bk, nullptr, nullptr, pk, BNROWS, DD, DD);
    gemm128<0><<<dim3(DD / 128, BNROWS / 128), 256>>>(pxn, Wv, bv, nullptr, nullptr, pv, BNROWS, DD, DD);
    // 3) per-edge bias (eb + geo-LN proj)
    edge_bias_kernel<<<(BB * EE) / 8, 256>>>(rel, geo, W_eb, b_eb, geog, geob, W_geo, b_geo);
    // 4) parallel ordered scatter: winner map + dense fill
    wmap_init_kernel<<<(BB * NNODE * NNODE) / 256, 256>>>();
    wmap_scatter_kernel<<<(BB * EE) / 256, 256>>>(edges, emask);
    bm_fill_kernel<<<(BB * NNODE * NNODE) / 256, 256>>>(nmask);
    // 5) fused attention
    int attn_smem = (64 * KT_PITCH + 256 * 64 + 8 * 64 + 8 * 256) * 4;
    cudaFuncSetAttribute(attn_kernel, cudaFuncAttributeMaxDynamicSharedMemorySize, attn_smem);
    attn_kernel<<<BB * HH, 256, attn_smem>>>();
    // 6) output projection + residual
    gemm128<1><<<dim3(DD / 128, BNROWS / 128), 256>>>(patt, W_out, b_out, x, nullptr, px2, BNROWS, DD, DD);
    // 7) FF block
    ln_kernel<<<BNROWS, 128>>>(px2, fg, fb, pln2);
    gemm128<2><<<dim3(DFF / 128, BNROWS / 128), 256>>>(pln2, W1, b1, nullptr, nullptr, ph1, BNROWS, DFF, DD);
    gemm128<3><<<dim3(DD / 128, BNROWS / 128), 256>>>(ph1, W2, b2, px2, nmask, out, BNROWS, DD, DFF);
}

// round 4
// speedup vs baseline: 2.8486x; 1.4265x over previous
#include <cuda_runtime.h>
#include <cuda_bf16.h>
#include <math.h>
#include <float.h>
#include <stdint.h>

// Problem constants
#define BB    32
#define NNODE 256
#define DD    512
#define HH    8
#define EE    1024
#define EDIM  256
#define GDIM  64
#define HDIM  64
#define BNROWS (BB*NNODE)   // 8192
#define DFF   2048

// ---------------- scratch (device globals; no runtime alloc) ----------------
__device__ float g_xn [BNROWS*DD];
__device__ float g_q  [BNROWS*DD];
__device__ float g_k  [BNROWS*DD];
__device__ float g_v  [BNROWS*DD];
__device__ float g_att[BNROWS*DD];
__device__ float g_x2 [BNROWS*DD];
__device__ float g_ln2[BNROWS*DD];
__device__ float g_h1 [BNROWS*DFF];
__device__ float g_ebias[BB*EE*HH];
__device__ int   g_wmap[BB*NNODE*NNODE];            // winner edge position per (b,i,j)
__device__ float g_bm[(size_t)BB*HH*NNODE*NNODE];   // fused bias + mask (-FLT_MAX = masked)

// ---------------- LayerNorm: one block per row of 512 ----------------
__global__ void ln_kernel(const float* __restrict__ x, const float* __restrict__ g,
                          const float* __restrict__ b, float* __restrict__ y) {
    int row = blockIdx.x;
    const float* xr = x + (size_t)row * DD;
    float* yr = y + (size_t)row * DD;
    int tid = threadIdx.x; // 128
    float v[4];
    float s = 0.f, s2 = 0.f;
#pragma unroll
    for (int i = 0; i < 4; i++) {
        v[i] = xr[tid + i * 128];
        s += v[i]; s2 += v[i] * v[i];
    }
    __shared__ float rs[4], rs2[4];
    for (int o = 16; o; o >>= 1) {
        s  += __shfl_xor_sync(~0u, s,  o);
        s2 += __shfl_xor_sync(~0u, s2, o);
    }
    int w = tid >> 5;
    if ((tid & 31) == 0) { rs[w] = s; rs2[w] = s2; }
    __syncthreads();
    s  = rs[0] + rs[1] + rs[2] + rs[3];
    s2 = rs2[0] + rs2[1] + rs2[2] + rs2[3];
    float mean = s * (1.f / DD);
    float var  = s2 * (1.f / DD) - mean * mean;
    float r = rsqrtf(var + 1e-5f);
#pragma unroll
    for (int i = 0; i < 4; i++) {
        int c = tid + i * 128;
        yr[c] = (v[i] - mean) * r * g[c] + b[c];
    }
}

// ================= tensor-core GEMM (bf16 hi/lo split, 3-MMA, fp32 accum) ===============
// C = A(MxK) @ W(NoutxK)^T + bias. EPI: 0=bias, 1=+res, 2=silu, 3=+res then *rowscale
#define PITCH 40   // bf16 elements per smem row (32 data + 8 pad); 80 B pitch

__device__ __forceinline__ void ldsm4(uint32_t a, uint32_t& r0, uint32_t& r1,
                                      uint32_t& r2, uint32_t& r3) {
    asm volatile("ldmatrix.sync.aligned.m8n8.x4.shared.b16 {%0,%1,%2,%3}, [%4];"
                 : "=r"(r0), "=r"(r1), "=r"(r2), "=r"(r3) : "r"(a));
}

__device__ __forceinline__ void mma16816(float (&d)[4], const uint32_t (&a)[4],
                                         const uint32_t* b) {
    asm volatile("mma.sync.aligned.m16n8k16.row.col.f32.bf16.bf16.f32 "
                 "{%0,%1,%2,%3}, {%4,%5,%6,%7}, {%8,%9}, {%0,%1,%2,%3};"
                 : "+f"(d[0]), "+f"(d[1]), "+f"(d[2]), "+f"(d[3])
                 : "r"(a[0]), "r"(a[1]), "r"(a[2]), "r"(a[3]), "r"(b[0]), "r"(b[1]));
}

__device__ __forceinline__ void splits(float4 v, uint32_t* hp, uint32_t* lp) {
    __nv_bfloat16 hx = __float2bfloat16_rn(v.x), hy = __float2bfloat16_rn(v.y);
    __nv_bfloat16 hz = __float2bfloat16_rn(v.z), hw = __float2bfloat16_rn(v.w);
    __nv_bfloat16 lx = __float2bfloat16_rn(v.x - __bfloat162float(hx));
    __nv_bfloat16 ly = __float2bfloat16_rn(v.y - __bfloat162float(hy));
    __nv_bfloat16 lz = __float2bfloat16_rn(v.z - __bfloat162float(hz));
    __nv_bfloat16 lw = __float2bfloat16_rn(v.w - __bfloat162float(hw));
    __nv_bfloat162 h01(hx, hy), h23(hz, hw), l01(lx, ly), l23(lz, lw);
    hp[0] = *(uint32_t*)&h01; hp[1] = *(uint32_t*)&h23;
    lp[0] = *(uint32_t*)&l01; lp[1] = *(uint32_t*)&l23;
}

template<int EPI>
__global__ void __launch_bounds__(256, 1)
gemm_mma(const float* __restrict__ A, const float* __restrict__ W,
         const float* __restrict__ bias, const float* __restrict__ res,
         const float* __restrict__ rowscale, float* __restrict__ C,
         int M, int Nout, int K) {
    __shared__ __align__(16) __nv_bfloat16 Ah[128 * PITCH], Al[128 * PITCH];
    __shared__ __align__(16) __nv_bfloat16 Bh[128 * PITCH], Bl[128 * PITCH];

    int tid = threadIdx.x;               // 256 = 8 warps (4x2)
    int warp = tid >> 5, lane = tid & 31;
    int wm = warp >> 1, wn = warp & 1;
    int bm0 = blockIdx.y * 128, bn0 = blockIdx.x * 128;

    int lr = tid >> 3;                   // 0..31 (gmem load row)
    int lk = (tid & 7) << 2;             // 0..28 (gmem load k-offset)

    const float* Ap = A + (size_t)(bm0 + lr) * K + lk;
    const float* Wp = W + (size_t)(bn0 + lr) * K + lk;

    float acc[2][8][4];
#pragma unroll
    for (int i = 0; i < 2; i++)
#pragma unroll
        for (int j = 0; j < 8; j++)
#pragma unroll
            for (int r = 0; r < 4; r++) acc[i][j][r] = 0.f;

    uint32_t sAh = (uint32_t)__cvta_generic_to_shared(Ah);
    uint32_t sAl = (uint32_t)__cvta_generic_to_shared(Al);
    uint32_t sBh = (uint32_t)__cvta_generic_to_shared(Bh);
    uint32_t sBl = (uint32_t)__cvta_generic_to_shared(Bl);

    // ldmatrix per-lane address components
    int a_r  = lane & 15;
    int a_cb = (lane >> 4) << 4;                       // 0 or 16 bytes
    uint32_t aOffH = (uint32_t)((wm * 32 + a_r) * (PITCH * 2) + a_cb);
    int b_r  = ((lane >> 4) & 1) * 8 + (lane & 7);
    int b_cb = ((lane >> 3) & 1) << 4;
    uint32_t bOffH = (uint32_t)((wn * 64 + b_r) * (PITCH * 2) + b_cb);

    for (int k0 = 0; k0 < K; k0 += 32) {
        float4 av[4], wv[4];
#pragma unroll
        for (int r = 0; r < 4; r++) {
            av[r] = *(const float4*)(Ap + (size_t)(r * 32) * K + k0);
            wv[r] = *(const float4*)(Wp + (size_t)(r * 32) * K + k0);
        }
        __syncthreads();
#pragma unroll
        for (int r = 0; r < 4; r++) {
            int row = lr + r * 32;
            splits(av[r], (uint32_t*)&Ah[row * PITCH + lk], (uint32_t*)&Al[row * PITCH + lk]);
            splits(wv[r], (uint32_t*)&Bh[row * PITCH + lk], (uint32_t*)&Bl[row * PITCH + lk]);
        }
        __syncthreads();
#pragma unroll
        for (int ks = 0; ks < 2; ks++) {
            uint32_t kb = (uint32_t)(ks * 32);
            uint32_t ah[2][4], al[2][4], bh[8][2], bl[8][2];
#pragma unroll
            for (int mi = 0; mi < 2; mi++) {
                uint32_t off = aOffH + (uint32_t)(mi * 16 * PITCH * 2) + kb;
                ldsm4(sAh + off, ah[mi][0], ah[mi][1], ah[mi][2], ah[mi][3]);
                ldsm4(sAl + off, al[mi][0], al[mi][1], al[mi][2], al[mi][3]);
            }
#pragma unroll
            for (int bp = 0; bp < 4; bp++) {
                uint32_t off = bOffH + (uint32_t)(bp * 16 * PITCH * 2) + kb;
                ldsm4(sBh + off, bh[2*bp][0], bh[2*bp][1], bh[2*bp+1][0], bh[2*bp+1][1]);
                ldsm4(sBl + off, bl[2*bp][0], bl[2*bp][1], bl[2*bp+1][0], bl[2*bp+1][1]);
            }
#pragma unroll
            for (int mi = 0; mi < 2; mi++)
#pragma unroll
                for (int ni = 0; ni < 8; ni++) {
                    mma16816(acc[mi][ni], ah[mi], bh[ni]);   // hi*hi
                    mma16816(acc[mi][ni], ah[mi], bl[ni]);   // hi*lo
                    mma16816(acc[mi][ni], al[mi], bh[ni]);   // lo*hi
                }
        }
    }

    // epilogue
    int qr = lane >> 2, qc = (lane & 3) << 1;
#pragma unroll
    for (int mi = 0; mi < 2; mi++) {
        int m0 = bm0 + wm * 32 + mi * 16 + qr;
#pragma unroll
        for (int ni = 0; ni < 8; ni++) {
            int n = bn0 + wn * 64 + ni * 8 + qc;
            float b0 = bias[n], b1 = bias[n + 1];
#pragma unroll
            for (int rr = 0; rr < 2; rr++) {
                int m = m0 + rr * 8;
                float v0 = acc[mi][ni][rr * 2 + 0] + b0;
                float v1 = acc[mi][ni][rr * 2 + 1] + b1;
                if (EPI == 1 || EPI == 3) {
                    v0 += res[(size_t)m * Nout + n];
                    v1 += res[(size_t)m * Nout + n + 1];
                }
                if (EPI == 2) {
                    v0 = v0 / (1.f + expf(-v0));
                    v1 = v1 / (1.f + expf(-v1));
                }
                if (EPI == 3) { float rsc = rowscale[m]; v0 *= rsc; v1 *= rsc; }
                *(float2*)(C + (size_t)m * Nout + n) = make_float2(v0, v1);
            }
        }
    }
}

// ---------------- Edge bias: one warp per (b,e) ----------------
__global__ void edge_bias_kernel(const float* __restrict__ rel, const float* __restrict__ geo,
                                 const float* __restrict__ W_eb, const float* __restrict__ b_eb,
                                 const float* __restrict__ geog, const float* __restrict__ geob,
                                 const float* __restrict__ W_geo, const float* __restrict__ b_geo) {
    int warp = (blockIdx.x * blockDim.x + threadIdx.x) >> 5;
    int lane = threadIdx.x & 31;
    if (warp >= BB * EE) return;
    const float* re = rel + (size_t)warp * EDIM;
    const float* ge = geo + (size_t)warp * GDIM;
    float acc[8] = {0, 0, 0, 0, 0, 0, 0, 0};
#pragma unroll
    for (int it = 0; it < 8; it++) {
        int c = (it << 5) + lane;
        float xv = re[c];
#pragma unroll
        for (int h = 0; h < 8; h++) acc[h] += xv * W_eb[h * EDIM + c];
    }
    float g0 = ge[lane], g1 = ge[lane + 32];
    float s = g0 + g1, s2 = g0 * g0 + g1 * g1;
    for (int o = 16; o; o >>= 1) {
        s  += __shfl_xor_sync(~0u, s,  o);
        s2 += __shfl_xor_sync(~0u, s2, o);
    }
    float mean = s * (1.f / 64.f);
    float var  = s2 * (1.f / 64.f) - mean * mean;
    float r = rsqrtf(var + 1e-5f);
    float n0 = (g0 - mean) * r * geog[lane]      + geob[lane];
    float n1 = (g1 - mean) * r * geog[lane + 32] + geob[lane + 32];
#pragma unroll
    for (int h = 0; h < 8; h++)
        acc[h] += n0 * W_geo[h * GDIM + lane] + n1 * W_geo[h * GDIM + lane + 32];
#pragma unroll
    for (int h = 0; h < 8; h++) {
        float v = acc[h];
        for (int o = 16; o; o >>= 1) v += __shfl_xor_sync(~0u, v, o);
        if (lane == h) g_ebias[(size_t)warp * HH + h] = v + b_eb[h] + b_geo[h];
    }
}

// ---------------- winner map: init to -1 ----------------
__global__ void wmap_init_kernel() {
    int idx = blockIdx.x * 256 + threadIdx.x;
    g_wmap[idx] = -1;
}

// ---------------- parallel ordered-scatter via atomicMax on sequence position ----------------
__global__ void wmap_scatter_kernel(const int* __restrict__ edges, const float* __restrict__ emask) {
    int t = blockIdx.x * 256 + threadIdx.x;   // B*E
    if (t >= BB * EE) return;
    int b = t >> 10, e = t & 1023;
    if (emask[t] > 0.5f) {
        int s = min(max(edges[2 * t], 0), NNODE - 1);
        int d = min(max(edges[2 * t + 1], 0), NNODE - 1);
        atomicMax(&g_wmap[b * 65536 + s * 256 + d], e);
        atomicMax(&g_wmap[b * 65536 + d * 256 + s], e + EE);
    }
}

// ---------------- dense fill of fused bias/mask (node mask folded in) ----------------
__global__ void bm_fill_kernel(const float* __restrict__ nmask) {
    int idx = blockIdx.x * 256 + threadIdx.x;   // B*N*N
    int j = idx & 255, i = (idx >> 8) & 255, b = idx >> 16;
    int w = g_wmap[idx];
    bool ok = (nmask[b * 256 + i] != 0.f) && (nmask[b * 256 + j] != 0.f) && (w >= 0 || i == j);
    float* bm = g_bm + (size_t)b * HH * 65536 + i * 256 + j;
    if (!ok) {
#pragma unroll
        for (int h = 0; h < HH; h++) bm[(size_t)h * 65536] = -FLT_MAX;
    } else if (w < 0) {
#pragma unroll
        for (int h = 0; h < HH; h++) bm[(size_t)h * 65536] = 0.f;
    } else {
        int e = (w >= EE) ? w - EE : w;
        const float* eb = g_ebias + ((size_t)b * EE + e) * HH;
#pragma unroll
        for (int h = 0; h < HH; h++) bm[(size_t)h * 65536] = eb[h];
    }
}

// ---------------- fused attention: one block per (b,h); warp per query row ----------------
#define KT_PITCH 260
__global__ void attn_kernel() {
    extern __shared__ float smem[];
    float* kt = smem;                       // 64*260
    float* vs = kt + 64 * KT_PITCH;         // 256*64
    float* qs = vs + 256 * 64;              // 8*64
    float* ps = qs + 8 * 64;                // 8*256

    int bh = blockIdx.x;
    int b = bh >> 3, h = bh & 7;
    int tid = threadIdx.x;                  // 256
    int w = tid >> 5, lane = tid & 31;

    for (int idx = tid; idx < 256 * 64; idx += 256) {
        int j = idx >> 6, d = idx & 63;
        size_t off = (size_t)(b * NNODE + j) * DD + h * HDIM + d;
        kt[d * KT_PITCH + j] = g_k[off];
        vs[j * 64 + d]       = g_v[off];
    }
    __syncthreads();

    const float* bmB = g_bm + (size_t)bh * 65536;
    float* psw = ps + w * 256;
    float* qsw = qs + w * 64;

    for (int i = w * 32; i < w * 32 + 32; i++) {
        size_t qoff = (size_t)(b * NNODE + i) * DD + h * HDIM;
        qsw[lane]      = g_q[qoff + lane];
        qsw[lane + 32] = g_q[qoff + lane + 32];
        __syncwarp();

        float4 bm0 = *(const float4*)&bmB[i * 256 + (lane << 2)];
        float4 bm1 = *(const float4*)&bmB[i * 256 + 128 + (lane << 2)];

        float s[8] = {0, 0, 0, 0, 0, 0, 0, 0};
#pragma unroll 8
        for (int d = 0; d < 64; d++) {
            float qd = qsw[d];
            float4 k0 = *(const float4*)&kt[d * KT_PITCH + (lane << 2)];
            float4 k1 = *(const float4*)&kt[d * KT_PITCH + 128 + (lane << 2)];
            s[0] += qd * k0.x; s[1] += qd * k0.y; s[2] += qd * k0.z; s[3] += qd * k0.w;
            s[4] += qd * k1.x; s[5] += qd * k1.y; s[6] += qd * k1.z; s[7] += qd * k1.w;
        }
        float sc[8];
        const float* bmv0 = &bm0.x;
        const float* bmv1 = &bm1.x;
#pragma unroll
        for (int r = 0; r < 4; r++) {
            sc[r]     = (bmv0[r] == -FLT_MAX) ? -FLT_MAX : s[r]     * 0.125f + bmv0[r];
            sc[4 + r] = (bmv1[r] == -FLT_MAX) ? -FLT_MAX : s[4 + r] * 0.125f + bmv1[r];
        }
        float mx = sc[0];
#pragma unroll
        for (int r = 1; r < 8; r++) mx = fmaxf(mx, sc[r]);
        for (int o = 16; o; o >>= 1) mx = fmaxf(mx, __shfl_xor_sync(~0u, mx, o));
        float p[8], sum = 0.f;
#pragma unroll
        for (int r = 0; r < 8; r++) { p[r] = expf(sc[r] - mx); sum += p[r]; }
        for (int o = 16; o; o >>= 1) sum += __shfl_xor_sync(~0u, sum, o);
        float inv = 1.f / sum;

        *(float4*)&psw[lane << 2]         = make_float4(p[0], p[1], p[2], p[3]);
        *(float4*)&psw[128 + (lane << 2)] = make_float4(p[4], p[5], p[6], p[7]);
        __syncwarp();

        int d0 = lane << 1;
        float o0 = 0.f, o1 = 0.f;
#pragma unroll 4
        for (int j0 = 0; j0 < 256; j0 += 4) {
            float4 p4 = *(const float4*)&psw[j0];
            float2 v0 = *(const float2*)&vs[(j0 + 0) * 64 + d0];
            float2 v1 = *(const float2*)&vs[(j0 + 1) * 64 + d0];
            float2 v2 = *(const float2*)&vs[(j0 + 2) * 64 + d0];
            float2 v3 = *(const float2*)&vs[(j0 + 3) * 64 + d0];
            o0 += p4.x * v0.x + p4.y * v1.x + p4.z * v2.x + p4.w * v3.x;
            o1 += p4.x * v0.y + p4.y * v1.y + p4.z * v2.y + p4.w * v3.y;
        }
        *(float2*)&g_att[qoff + d0] = make_float2(o0 * inv, o1 * inv);
        __syncwarp();
    }
}

// ---------------- host launcher ----------------
extern "C" void kernel_launch(void* const* d_in, const int* in_sizes, int n_in,
                              void* d_out, int out_size) {
    const float* x     = (const float*)d_in[0];
    const float* nmask = (const float*)d_in[1];
    const int*   edges = (const int*)  d_in[2];
    const float* emask = (const float*)d_in[3];
    const float* rel   = (const float*)d_in[4];
    const float* geo   = (const float*)d_in[5];
    const float* Wq = (const float*)d_in[6];  const float* bq = (const float*)d_in[7];
    const float* Wk = (const float*)d_in[8];  const float* bk = (const float*)d_in[9];
    const float* Wv = (const float*)d_in[10]; const float* bv = (const float*)d_in[11];
    const float* W_eb = (const float*)d_in[12]; const float* b_eb = (const float*)d_in[13];
    const float* geog = (const float*)d_in[14]; const float* geob = (const float*)d_in[15];
    const float* W_geo = (const float*)d_in[16]; const float* b_geo = (const float*)d_in[17];
    const float* W_out = (const float*)d_in[18]; const float* b_out = (const float*)d_in[19];
    const float* ng = (const float*)d_in[20]; const float* nb = (const float*)d_in[21];
    const float* fg = (const float*)d_in[22]; const float* fb = (const float*)d_in[23];
    const float* W1 = (const float*)d_in[24]; const float* b1 = (const float*)d_in[25];
    const float* W2 = (const float*)d_in[26]; const float* b2 = (const float*)d_in[27];
    float* out = (float*)d_out;

    float *pxn, *pq, *pk, *pv, *patt, *px2, *pln2, *ph1;
    cudaGetSymbolAddress((void**)&pxn,  g_xn);
    cudaGetSymbolAddress((void**)&pq,   g_q);
    cudaGetSymbolAddress((void**)&pk,   g_k);
    cudaGetSymbolAddress((void**)&pv,   g_v);
    cudaGetSymbolAddress((void**)&patt, g_att);
    cudaGetSymbolAddress((void**)&px2,  g_x2);
    cudaGetSymbolAddress((void**)&pln2, g_ln2);
    cudaGetSymbolAddress((void**)&ph1,  g_h1);

    // 1) pre-LN
    ln_kernel<<<BNROWS, 128>>>(x, ng, nb, pxn);
    // 2) Q,K,V projections (tensor cores)
    gemm_mma<0><<<dim3(DD / 128, BNROWS / 128), 256>>>(pxn, Wq, bq, nullptr, nullptr, pq, BNROWS, DD, DD);
    gemm_mma<0><<<dim3(DD / 128, BNROWS / 128), 256>>>(pxn, Wk, bk, nullptr, nullptr, pk, BNROWS, DD, DD);
    gemm_mma<0><<<dim3(DD / 128, BNROWS / 128), 256>>>(pxn, Wv, bv, nullptr, nullptr, pv, BNROWS, DD, DD);
    // 3) per-edge bias (eb + geo-LN proj)
    edge_bias_kernel<<<(BB * EE) / 8, 256>>>(rel, geo, W_eb, b_eb, geog, geob, W_geo, b_geo);
    // 4) parallel ordered scatter: winner map + dense fill
    wmap_init_kernel<<<(BB * NNODE * NNODE) / 256, 256>>>();
    wmap_scatter_kernel<<<(BB * EE) / 256, 256>>>(edges, emask);
    bm_fill_kernel<<<(BB * NNODE * NNODE) / 256, 256>>>(nmask);
    // 5) fused attention
    int attn_smem = (64 * KT_PITCH + 256 * 64 + 8 * 64 + 8 * 256) * 4;
    cudaFuncSetAttribute(attn_kernel, cudaFuncAttributeMaxDynamicSharedMemorySize, attn_smem);
    attn_kernel<<<BB * HH, 256, attn_smem>>>();
    // 6) output projection + residual
    gemm_mma<1><<<dim3(DD / 128, BNROWS / 128), 256>>>(patt, W_out, b_out, x, nullptr, px2, BNROWS, DD, DD);
    // 7) FF block
    ln_kernel<<<BNROWS, 128>>>(px2, fg, fb, pln2);
    gemm_mma<2><<<dim3(DFF / 128, BNROWS / 128), 256>>>(pln2, W1, b1, nullptr, nullptr, ph1, BNROWS, DFF, DD);
    gemm_mma<3><<<dim3(DD / 128, BNROWS / 128), 256>>>(ph1, W2, b2, px2, nmask, out, BNROWS, DD, DFF);
}

// round 5
// speedup vs baseline: 3.0724x; 1.0786x over previous
#include <cuda_runtime.h>
#include <cuda_bf16.h>
#include <math.h>
#include <float.h>
#include <stdint.h>

// Problem constants
#define BB    32
#define NNODE 256
#define DD    512
#define HH    8
#define EE    1024
#define EDIM  256
#define GDIM  64
#define HDIM  64
#define BNROWS (BB*NNODE)   // 8192
#define DFF   2048

// ---------------- scratch (device globals; no runtime alloc) ----------------
__device__ float g_q  [BNROWS*DD];
__device__ float g_k  [BNROWS*DD];
__device__ float g_v  [BNROWS*DD];
__device__ float g_x2 [BNROWS*DD];
__device__ float g_ebias[BB*EE*HH];
__device__ int   g_wmap[BB*NNODE*NNODE];
__device__ float g_bm[(size_t)BB*HH*NNODE*NNODE];

// pre-split bf16 hi/lo activation + weight buffers
__device__ __nv_bfloat16 g_xnh [BNROWS*DD],  g_xnl [BNROWS*DD];
__device__ __nv_bfloat16 g_atth[BNROWS*DD],  g_attl[BNROWS*DD];
__device__ __nv_bfloat16 g_ln2h[BNROWS*DD],  g_ln2l[BNROWS*DD];
__device__ __nv_bfloat16 g_h1h [BNROWS*DFF], g_h1l [BNROWS*DFF];
__device__ __nv_bfloat16 g_wqh[DD*DD], g_wql[DD*DD];
__device__ __nv_bfloat16 g_wkh[DD*DD], g_wkl[DD*DD];
__device__ __nv_bfloat16 g_wvh[DD*DD], g_wvl[DD*DD];
__device__ __nv_bfloat16 g_woh[DD*DD], g_wol[DD*DD];
__device__ __nv_bfloat16 g_w1h[DFF*DD], g_w1l[DFF*DD];
__device__ __nv_bfloat16 g_w2h[DD*DFF], g_w2l[DD*DFF];

// ---------------- fp32 -> bf16 hi/lo split ----------------
__global__ void split_kernel(const float* __restrict__ src, __nv_bfloat16* __restrict__ h,
                             __nv_bfloat16* __restrict__ l, int n) {
    int i = blockIdx.x * 256 + threadIdx.x;
    if (i < n) {
        float v = src[i];
        __nv_bfloat16 hh = __float2bfloat16_rn(v);
        h[i] = hh;
        l[i] = __float2bfloat16_rn(v - __bfloat162float(hh));
    }
}

// ---------------- LayerNorm -> bf16 hi/lo: one block per row of 512 ----------------
__global__ void ln_bf16_kernel(const float* __restrict__ x, const float* __restrict__ g,
                               const float* __restrict__ b, __nv_bfloat16* __restrict__ yh,
                               __nv_bfloat16* __restrict__ yl) {
    int row = blockIdx.x;
    const float* xr = x + (size_t)row * DD;
    int tid = threadIdx.x; // 128
    float v[4];
    float s = 0.f, s2 = 0.f;
#pragma unroll
    for (int i = 0; i < 4; i++) {
        v[i] = xr[tid + i * 128];
        s += v[i]; s2 += v[i] * v[i];
    }
    __shared__ float rs[4], rs2[4];
    for (int o = 16; o; o >>= 1) {
        s  += __shfl_xor_sync(~0u, s,  o);
        s2 += __shfl_xor_sync(~0u, s2, o);
    }
    int w = tid >> 5;
    if ((tid & 31) == 0) { rs[w] = s; rs2[w] = s2; }
    __syncthreads();
    s  = rs[0] + rs[1] + rs[2] + rs[3];
    s2 = rs2[0] + rs2[1] + rs2[2] + rs2[3];
    float mean = s * (1.f / DD);
    float var  = s2 * (1.f / DD) - mean * mean;
    float r = rsqrtf(var + 1e-5f);
#pragma unroll
    for (int i = 0; i < 4; i++) {
        int c = tid + i * 128;
        float y = (v[i] - mean) * r * g[c] + b[c];
        __nv_bfloat16 hh = __float2bfloat16_rn(y);
        yh[(size_t)row * DD + c] = hh;
        yl[(size_t)row * DD + c] = __float2bfloat16_rn(y - __bfloat162float(hh));
    }
}

// ================= pipelined tensor-core GEMM (pre-split bf16, 3-MMA, fp32 accum) =========
// C = A(MxK) @ W(NoutxK)^T + bias. EPI: 0=bias->f32, 1=+res->f32, 2=silu->bf16 hi/lo, 3=+res,*rowscale->f32
#define PITCH 40   // bf16 per smem row (32 data + 8 pad) = 80 B

#define CP16(dst, src) \
    asm volatile("cp.async.cg.shared.global [%0], [%1], 16;" :: "r"(dst), "l"(src))

__device__ __forceinline__ void ldsm4(uint32_t a, uint32_t& r0, uint32_t& r1,
                                      uint32_t& r2, uint32_t& r3) {
    asm volatile("ldmatrix.sync.aligned.m8n8.x4.shared.b16 {%0,%1,%2,%3}, [%4];"
                 : "=r"(r0), "=r"(r1), "=r"(r2), "=r"(r3) : "r"(a));
}

__device__ __forceinline__ void mma16816(float (&d)[4], const uint32_t (&a)[4],
                                         const uint32_t* b) {
    asm volatile("mma.sync.aligned.m16n8k16.row.col.f32.bf16.bf16.f32 "
                 "{%0,%1,%2,%3}, {%4,%5,%6,%7}, {%8,%9}, {%0,%1,%2,%3};"
                 : "+f"(d[0]), "+f"(d[1]), "+f"(d[2]), "+f"(d[3])
                 : "r"(a[0]), "r"(a[1]), "r"(a[2]), "r"(a[3]), "r"(b[0]), "r"(b[1]));
}

// stage layout (bytes): Ah @0, Al @10240, Bh @20480, Bl @30720 ; stage stride 40960
template<int EPI>
__global__ void __launch_bounds__(256, 1)
gemm_bf16(const __nv_bfloat16* __restrict__ Ah_g, const __nv_bfloat16* __restrict__ Al_g,
          const __nv_bfloat16* __restrict__ Bh_g, const __nv_bfloat16* __restrict__ Bl_g,
          const float* __restrict__ bias, const float* __restrict__ res,
          const float* __restrict__ rowscale, float* __restrict__ C,
          __nv_bfloat16* __restrict__ Ch, __nv_bfloat16* __restrict__ Cl,
          int M, int Nout, int K) {
    extern __shared__ __align__(16) __nv_bfloat16 sm[];
    uint32_t smBase = (uint32_t)__cvta_generic_to_shared(sm);

    int tid = threadIdx.x;               // 256 = 8 warps (4x2)
    int warp = tid >> 5, lane = tid & 31;
    int wm = warp >> 1, wn = warp & 1;
    int bm0 = blockIdx.y * 128, bn0 = blockIdx.x * 128;

    float acc[2][8][4];
#pragma unroll
    for (int i = 0; i < 2; i++)
#pragma unroll
        for (int j = 0; j < 8; j++)
#pragma unroll
            for (int r = 0; r < 4; r++) acc[i][j][r] = 0.f;

    // cp.async tile issue: 512 16B-chunks per array, 2 per thread
    int row0 = tid >> 2, cc0 = (tid & 3);
    int row1 = (tid + 256) >> 2, cc1 = cc0;   // chunk idx tid+256: row=+64, same cc
    // (tid+256)>>2 = row0+64 ; (tid+256)&3 = cc0

    // ldmatrix per-lane address components (byte offsets within a stage array)
    int a_r  = lane & 15;
    int a_cb = (lane >> 4) << 4;
    uint32_t aOffH = (uint32_t)((wm * 32 + a_r) * (PITCH * 2) + a_cb);
    int b_r  = ((lane >> 4) & 1) * 8 + (lane & 7);
    int b_cb = ((lane >> 3) & 1) << 4;
    uint32_t bOffH = (uint32_t)((wn * 64 + b_r) * (PITCH * 2) + b_cb);

    auto issue_tile = [&](int s, int k0) {
        uint32_t st = smBase + (uint32_t)s * 40960u;
        uint32_t so0 = (uint32_t)((row0 * PITCH + cc0 * 8) * 2);
        uint32_t so1 = (uint32_t)((row1 * PITCH + cc1 * 8) * 2);
        size_t ga0 = (size_t)(bm0 + row0) * K + k0 + cc0 * 8;
        size_t ga1 = (size_t)(bm0 + row1) * K + k0 + cc1 * 8;
        size_t gb0 = (size_t)(bn0 + row0) * K + k0 + cc0 * 8;
        size_t gb1 = (size_t)(bn0 + row1) * K + k0 + cc1 * 8;
        CP16(st + so0,          Ah_g + ga0);
        CP16(st + so1,          Ah_g + ga1);
        CP16(st + 10240 + so0,  Al_g + ga0);
        CP16(st + 10240 + so1,  Al_g + ga1);
        CP16(st + 20480 + so0,  Bh_g + gb0);
        CP16(st + 20480 + so1,  Bh_g + gb1);
        CP16(st + 30720 + so0,  Bl_g + gb0);
        CP16(st + 30720 + so1,  Bl_g + gb1);
    };

    issue_tile(0, 0);
    asm volatile("cp.async.commit_group;");
    issue_tile(1, 32);
    asm volatile("cp.async.commit_group;");

    int ktiles = K >> 5;
#pragma unroll 1
    for (int t = 0; t < ktiles; t++) {
        int s = t & 1;
        asm volatile("cp.async.wait_group 1;");
        __syncthreads();

        uint32_t pAh = smBase + (uint32_t)s * 40960u;
        uint32_t pAl = pAh + 10240u;
        uint32_t pBh = pAh + 20480u;
        uint32_t pBl = pAh + 30720u;
#pragma unroll
        for (int ks = 0; ks < 2; ks++) {
            uint32_t kb = (uint32_t)(ks * 32);
            uint32_t ah[2][4], al[2][4], bh[8][2], bl[8][2];
#pragma unroll
            for (int mi = 0; mi < 2; mi++) {
                uint32_t off = aOffH + (uint32_t)(mi * 16 * PITCH * 2) + kb;
                ldsm4(pAh + off, ah[mi][0], ah[mi][1], ah[mi][2], ah[mi][3]);
                ldsm4(pAl + off, al[mi][0], al[mi][1], al[mi][2], al[mi][3]);
            }
#pragma unroll
            for (int bp = 0; bp < 4; bp++) {
                uint32_t off = bOffH + (uint32_t)(bp * 16 * PITCH * 2) + kb;
                ldsm4(pBh + off, bh[2*bp][0], bh[2*bp][1], bh[2*bp+1][0], bh[2*bp+1][1]);
                ldsm4(pBl + off, bl[2*bp][0], bl[2*bp][1], bl[2*bp+1][0], bl[2*bp+1][1]);
            }
#pragma unroll
            for (int mi = 0; mi < 2; mi++)
#pragma unroll
                for (int ni = 0; ni < 8; ni++) {
                    mma16816(acc[mi][ni], ah[mi], bh[ni]);
                    mma16816(acc[mi][ni], ah[mi], bl[ni]);
                    mma16816(acc[mi][ni], al[mi], bh[ni]);
                }
        }
        __syncthreads();
        int nk = (t + 2) << 5;
        if (nk < K) issue_tile(s, nk);
        asm volatile("cp.async.commit_group;");
    }

    // epilogue
    int qr = lane >> 2, qc = (lane & 3) << 1;
#pragma unroll
    for (int mi = 0; mi < 2; mi++) {
        int m0 = bm0 + wm * 32 + mi * 16 + qr;
#pragma unroll
        for (int ni = 0; ni < 8; ni++) {
            int n = bn0 + wn * 64 + ni * 8 + qc;
            float b0 = bias[n], b1 = bias[n + 1];
#pragma unroll
            for (int rr = 0; rr < 2; rr++) {
                int m = m0 + rr * 8;
                float v0 = acc[mi][ni][rr * 2 + 0] + b0;
                float v1 = acc[mi][ni][rr * 2 + 1] + b1;
                if (EPI == 1 || EPI == 3) {
                    v0 += res[(size_t)m * Nout + n];
                    v1 += res[(size_t)m * Nout + n + 1];
                }
                if (EPI == 2) {
                    v0 = v0 / (1.f + expf(-v0));
                    v1 = v1 / (1.f + expf(-v1));
                    __nv_bfloat16 h0 = __float2bfloat16_rn(v0);
                    __nv_bfloat16 h1 = __float2bfloat16_rn(v1);
                    __nv_bfloat162 hh(h0, h1);
                    __nv_bfloat162 ll(__float2bfloat16_rn(v0 - __bfloat162float(h0)),
                                      __float2bfloat16_rn(v1 - __bfloat162float(h1)));
                    *(__nv_bfloat162*)(Ch + (size_t)m * Nout + n) = hh;
                    *(__nv_bfloat162*)(Cl + (size_t)m * Nout + n) = ll;
                } else {
                    if (EPI == 3) { float rsc = rowscale[m]; v0 *= rsc; v1 *= rsc; }
                    *(float2*)(C + (size_t)m * Nout + n) = make_float2(v0, v1);
                }
            }
        }
    }
}

// ---------------- Edge bias: one warp per (b,e) ----------------
__global__ void edge_bias_kernel(const float* __restrict__ rel, const float* __restrict__ geo,
                                 const float* __restrict__ W_eb, const float* __restrict__ b_eb,
                                 const float* __restrict__ geog, const float* __restrict__ geob,
                                 const float* __restrict__ W_geo, const float* __restrict__ b_geo) {
    int warp = (blockIdx.x * blockDim.x + threadIdx.x) >> 5;
    int lane = threadIdx.x & 31;
    if (warp >= BB * EE) return;
    const float* re = rel + (size_t)warp * EDIM;
    const float* ge = geo + (size_t)warp * GDIM;
    float acc[8] = {0, 0, 0, 0, 0, 0, 0, 0};
#pragma unroll
    for (int it = 0; it < 8; it++) {
        int c = (it << 5) + lane;
        float xv = re[c];
#pragma unroll
        for (int h = 0; h < 8; h++) acc[h] += xv * W_eb[h * EDIM + c];
    }
    float g0 = ge[lane], g1 = ge[lane + 32];
    float s = g0 + g1, s2 = g0 * g0 + g1 * g1;
    for (int o = 16; o; o >>= 1) {
        s  += __shfl_xor_sync(~0u, s,  o);
        s2 += __shfl_xor_sync(~0u, s2, o);
    }
    float mean = s * (1.f / 64.f);
    float var  = s2 * (1.f / 64.f) - mean * mean;
    float r = rsqrtf(var + 1e-5f);
    float n0 = (g0 - mean) * r * geog[lane]      + geob[lane];
    float n1 = (g1 - mean) * r * geog[lane + 32] + geob[lane + 32];
#pragma unroll
    for (int h = 0; h < 8; h++)
        acc[h] += n0 * W_geo[h * GDIM + lane] + n1 * W_geo[h * GDIM + lane + 32];
#pragma unroll
    for (int h = 0; h < 8; h++) {
        float v = acc[h];
        for (int o = 16; o; o >>= 1) v += __shfl_xor_sync(~0u, v, o);
        if (lane == h) g_ebias[(size_t)warp * HH + h] = v + b_eb[h] + b_geo[h];
    }
}

// ---------------- winner map + scatter + fill ----------------
__global__ void wmap_init_kernel() {
    int idx = blockIdx.x * 256 + threadIdx.x;
    g_wmap[idx] = -1;
}

__global__ void wmap_scatter_kernel(const int* __restrict__ edges, const float* __restrict__ emask) {
    int t = blockIdx.x * 256 + threadIdx.x;
    if (t >= BB * EE) return;
    int b = t >> 10, e = t & 1023;
    if (emask[t] > 0.5f) {
        int s = min(max(edges[2 * t], 0), NNODE - 1);
        int d = min(max(edges[2 * t + 1], 0), NNODE - 1);
        atomicMax(&g_wmap[b * 65536 + s * 256 + d], e);
        atomicMax(&g_wmap[b * 65536 + d * 256 + s], e + EE);
    }
}

__global__ void bm_fill_kernel(const float* __restrict__ nmask) {
    int idx = blockIdx.x * 256 + threadIdx.x;
    int j = idx & 255, i = (idx >> 8) & 255, b = idx >> 16;
    int w = g_wmap[idx];
    bool ok = (nmask[b * 256 + i] != 0.f) && (nmask[b * 256 + j] != 0.f) && (w >= 0 || i == j);
    float* bm = g_bm + (size_t)b * HH * 65536 + i * 256 + j;
    if (!ok) {
#pragma unroll
        for (int h = 0; h < HH; h++) bm[(size_t)h * 65536] = -FLT_MAX;
    } else if (w < 0) {
#pragma unroll
        for (int h = 0; h < HH; h++) bm[(size_t)h * 65536] = 0.f;
    } else {
        int e = (w >= EE) ? w - EE : w;
        const float* eb = g_ebias + ((size_t)b * EE + e) * HH;
#pragma unroll
        for (int h = 0; h < HH; h++) bm[(size_t)h * 65536] = eb[h];
    }
}

// ---------------- fused attention: one block per (b,h); warp per query row ----------------
#define KT_PITCH 260
__global__ void attn_kernel() {
    extern __shared__ float smem[];
    float* kt = smem;
    float* vs = kt + 64 * KT_PITCH;
    float* qs = vs + 256 * 64;
    float* ps = qs + 8 * 64;

    int bh = blockIdx.x;
    int b = bh >> 3, h = bh & 7;
    int tid = threadIdx.x;
    int w = tid >> 5, lane = tid & 31;

    for (int idx = tid; idx < 256 * 64; idx += 256) {
        int j = idx >> 6, d = idx & 63;
        size_t off = (size_t)(b * NNODE + j) * DD + h * HDIM + d;
        kt[d * KT_PITCH + j] = g_k[off];
        vs[j * 64 + d]       = g_v[off];
    }
    __syncthreads();

    const float* bmB = g_bm + (size_t)bh * 65536;
    float* psw = ps + w * 256;
    float* qsw = qs + w * 64;

    for (int i = w * 32; i < w * 32 + 32; i++) {
        size_t qoff = (size_t)(b * NNODE + i) * DD + h * HDIM;
        qsw[lane]      = g_q[qoff + lane];
        qsw[lane + 32] = g_q[qoff + lane + 32];
        __syncwarp();

        float4 bm0 = *(const float4*)&bmB[i * 256 + (lane << 2)];
        float4 bm1 = *(const float4*)&bmB[i * 256 + 128 + (lane << 2)];

        float s[8] = {0, 0, 0, 0, 0, 0, 0, 0};
#pragma unroll 8
        for (int d = 0; d < 64; d++) {
            float qd = qsw[d];
            float4 k0 = *(const float4*)&kt[d * KT_PITCH + (lane << 2)];
            float4 k1 = *(const float4*)&kt[d * KT_PITCH + 128 + (lane << 2)];
            s[0] += qd * k0.x; s[1] += qd * k0.y; s[2] += qd * k0.z; s[3] += qd * k0.w;
            s[4] += qd * k1.x; s[5] += qd * k1.y; s[6] += qd * k1.z; s[7] += qd * k1.w;
        }
        float sc[8];
        const float* bmv0 = &bm0.x;
        const float* bmv1 = &bm1.x;
#pragma unroll
        for (int r = 0; r < 4; r++) {
            sc[r]     = (bmv0[r] == -FLT_MAX) ? -FLT_MAX : s[r]     * 0.125f + bmv0[r];
            sc[4 + r] = (bmv1[r] == -FLT_MAX) ? -FLT_MAX : s[4 + r] * 0.125f + bmv1[r];
        }
        float mx = sc[0];
#pragma unroll
        for (int r = 1; r < 8; r++) mx = fmaxf(mx, sc[r]);
        for (int o = 16; o; o >>= 1) mx = fmaxf(mx, __shfl_xor_sync(~0u, mx, o));
        float p[8], sum = 0.f;
#pragma unroll
        for (int r = 0; r < 8; r++) { p[r] = expf(sc[r] - mx); sum += p[r]; }
        for (int o = 16; o; o >>= 1) sum += __shfl_xor_sync(~0u, sum, o);
        float inv = 1.f / sum;

        *(float4*)&psw[lane << 2]         = make_float4(p[0], p[1], p[2], p[3]);
        *(float4*)&psw[128 + (lane << 2)] = make_float4(p[4], p[5], p[6], p[7]);
        __syncwarp();

        int d0 = lane << 1;
        float o0 = 0.f, o1 = 0.f;
#pragma unroll 4
        for (int j0 = 0; j0 < 256; j0 += 4) {
            float4 p4 = *(const float4*)&psw[j0];
            float2 v0 = *(const float2*)&vs[(j0 + 0) * 64 + d0];
            float2 v1 = *(const float2*)&vs[(j0 + 1) * 64 + d0];
            float2 v2 = *(const float2*)&vs[(j0 + 2) * 64 + d0];
            float2 v3 = *(const float2*)&vs[(j0 + 3) * 64 + d0];
            o0 += p4.x * v0.x + p4.y * v1.x + p4.z * v2.x + p4.w * v3.x;
            o1 += p4.x * v0.y + p4.y * v1.y + p4.z * v2.y + p4.w * v3.y;
        }
        o0 *= inv; o1 *= inv;
        __nv_bfloat16 h0 = __float2bfloat16_rn(o0);
        __nv_bfloat16 h1 = __float2bfloat16_rn(o1);
        __nv_bfloat162 hh(h0, h1);
        __nv_bfloat162 ll(__float2bfloat16_rn(o0 - __bfloat162float(h0)),
                          __float2bfloat16_rn(o1 - __bfloat162float(h1)));
        *(__nv_bfloat162*)&g_atth[qoff + d0] = hh;
        *(__nv_bfloat162*)&g_attl[qoff + d0] = ll;
        __syncwarp();
    }
}

// ---------------- host launcher ----------------
extern "C" void kernel_launch(void* const* d_in, const int* in_sizes, int n_in,
                              void* d_out, int out_size) {
    const float* x     = (const float*)d_in[0];
    const float* nmask = (const float*)d_in[1];
    const int*   edges = (const int*)  d_in[2];
    const float* emask = (const float*)d_in[3];
    const float* rel   = (const float*)d_in[4];
    const float* geo   = (const float*)d_in[5];
    const float* Wq = (const float*)d_in[6];  const float* bq = (const float*)d_in[7];
    const float* Wk = (const float*)d_in[8];  const float* bk = (const float*)d_in[9];
    const float* Wv = (const float*)d_in[10]; const float* bv = (const float*)d_in[11];
    const float* W_eb = (const float*)d_in[12]; const float* b_eb = (const float*)d_in[13];
    const float* geog = (const float*)d_in[14]; const float* geob = (const float*)d_in[15];
    const float* W_geo = (const float*)d_in[16]; const float* b_geo = (const float*)d_in[17];
    const float* W_out = (const float*)d_in[18]; const float* b_out = (const float*)d_in[19];
    const float* ng = (const float*)d_in[20]; const float* nb = (const float*)d_in[21];
    const float* fg = (const float*)d_in[22]; const float* fb = (const float*)d_in[23];
    const float* W1 = (const float*)d_in[24]; const float* b1 = (const float*)d_in[25];
    const float* W2 = (const float*)d_in[26]; const float* b2 = (const float*)d_in[27];
    float* out = (float*)d_out;

    float *pq, *pk, *pv, *px2;
    cudaGetSymbolAddress((void**)&pq,  g_q);
    cudaGetSymbolAddress((void**)&pk,  g_k);
    cudaGetSymbolAddress((void**)&pv,  g_v);
    cudaGetSymbolAddress((void**)&px2, g_x2);
    __nv_bfloat16 *xnh, *xnl, *atth, *attl, *ln2h, *ln2l, *h1h, *h1l;
    __nv_bfloat16 *wqh, *wql, *wkh, *wkl, *wvh, *wvl, *woh, *wol, *w1h, *w1l, *w2h, *w2l;
    cudaGetSymbolAddress((void**)&xnh,  g_xnh);  cudaGetSymbolAddress((void**)&xnl,  g_xnl);
    cudaGetSymbolAddress((void**)&atth, g_atth); cudaGetSymbolAddress((void**)&attl, g_attl);
    cudaGetSymbolAddress((void**)&ln2h, g_ln2h); cudaGetSymbolAddress((void**)&ln2l, g_ln2l);
    cudaGetSymbolAddress((void**)&h1h,  g_h1h);  cudaGetSymbolAddress((void**)&h1l,  g_h1l);
    cudaGetSymbolAddress((void**)&wqh, g_wqh);   cudaGetSymbolAddress((void**)&wql, g_wql);
    cudaGetSymbolAddress((void**)&wkh, g_wkh);   cudaGetSymbolAddress((void**)&wkl, g_wkl);
    cudaGetSymbolAddress((void**)&wvh, g_wvh);   cudaGetSymbolAddress((void**)&wvl, g_wvl);
    cudaGetSymbolAddress((void**)&woh, g_woh);   cudaGetSymbolAddress((void**)&wol, g_wol);
    cudaGetSymbolAddress((void**)&w1h, g_w1h);   cudaGetSymbolAddress((void**)&w1l, g_w1l);
    cudaGetSymbolAddress((void**)&w2h, g_w2h);   cudaGetSymbolAddress((void**)&w2l, g_w2l);

    const int GSMEM = 81920;
    cudaFuncSetAttribute(gemm_bf16<0>, cudaFuncAttributeMaxDynamicSharedMemorySize, GSMEM);
    cudaFuncSetAttribute(gemm_bf16<1>, cudaFuncAttributeMaxDynamicSharedMemorySize, GSMEM);
    cudaFuncSetAttribute(gemm_bf16<2>, cudaFuncAttributeMaxDynamicSharedMemorySize, GSMEM);
    cudaFuncSetAttribute(gemm_bf16<3>, cudaFuncAttributeMaxDynamicSharedMemorySize, GSMEM);

    // 0) weight splits
    split_kernel<<<DD * DD / 256, 256>>>(Wq, wqh, wql, DD * DD);
    split_kernel<<<DD * DD / 256, 256>>>(Wk, wkh, wkl, DD * DD);
    split_kernel<<<DD * DD / 256, 256>>>(Wv, wvh, wvl, DD * DD);
    split_kernel<<<DD * DD / 256, 256>>>(W_out, woh, wol, DD * DD);
    split_kernel<<<DFF * DD / 256, 256>>>(W1, w1h, w1l, DFF * DD);
    split_kernel<<<DD * DFF / 256, 256>>>(W2, w2h, w2l, DD * DFF);
    // 1) pre-LN -> bf16 split
    ln_bf16_kernel<<<BNROWS, 128>>>(x, ng, nb, xnh, xnl);
    // 2) Q,K,V projections (pipelined tensor cores)
    gemm_bf16<0><<<dim3(DD / 128, BNROWS / 128), 256, GSMEM>>>(xnh, xnl, wqh, wql, bq, nullptr, nullptr, pq, nullptr, nullptr, BNROWS, DD, DD);
    gemm_bf16<0><<<dim3(DD / 128, BNROWS / 128), 256, GSMEM>>>(xnh, xnl, wkh, wkl, bk, nullptr, nullptr, pk, nullptr, nullptr, BNROWS, DD, DD);
    gemm_bf16<0><<<dim3(DD / 128, BNROWS / 128), 256, GSMEM>>>(xnh, xnl, wvh, wvl, bv, nullptr, nullptr, pv, nullptr, nullptr, BNROWS, DD, DD);
    // 3) per-edge bias
    edge_bias_kernel<<<(BB * EE) / 8, 256>>>(rel, geo, W_eb, b_eb, geog, geob, W_geo, b_geo);
    // 4) parallel ordered scatter
    wmap_init_kernel<<<(BB * NNODE * NNODE) / 256, 256>>>();
    wmap_scatter_kernel<<<(BB * EE) / 256, 256>>>(edges, emask);
    bm_fill_kernel<<<(BB * NNODE * NNODE) / 256, 256>>>(nmask);
    // 5) fused attention (writes bf16 hi/lo)
    int attn_smem = (64 * KT_PITCH + 256 * 64 + 8 * 64 + 8 * 256) * 4;
    cudaFuncSetAttribute(attn_kernel, cudaFuncAttributeMaxDynamicSharedMemorySize, attn_smem);
    attn_kernel<<<BB * HH, 256, attn_smem>>>();
    // 6) output projection + residual
    gemm_bf16<1><<<dim3(DD / 128, BNROWS / 128), 256, GSMEM>>>(atth, attl, woh, wol, b_out, x, nullptr, px2, nullptr, nullptr, BNROWS, DD, DD);
    // 7) FF block
    ln_bf16_kernel<<<BNROWS, 128>>>(px2, fg, fb, ln2h, ln2l);
    gemm_bf16<2><<<dim3(DFF / 128, BNROWS / 128), 256, GSMEM>>>(ln2h, ln2l, w1h, w1l, b1, nullptr, nullptr, nullptr, h1h, h1l, BNROWS, DFF, DD);
    gemm_bf16<3><<<dim3(DD / 128, BNROWS / 128), 256, GSMEM>>>(h1h, h1l, w2h, w2l, b2, px2, nmask, out, nullptr, nullptr, BNROWS, DD, DFF);
}